// round 10
// baseline (speedup 1.0000x reference)
#include <cuda_runtime.h>
#include <cuda_fp16.h>
#include <cstdint>

#define N_NODES 100000
#define N_EDGES 1250000
#define FEATS   64
#define CAP     64            // bucket capacity per node (Poisson(12.5): P(>63) ~ 1e-30)
#define GBN     128           // gemm nodes per block

// ---------------------------------------------------------------------------
// Device-global scratch (no allocations allowed).
// ---------------------------------------------------------------------------
__device__ int   g_count[N_NODES];              // per-node in-degree
__device__ int   g_bucket[N_NODES * CAP];       // src ids, fixed stride
__device__ uint4 g_hwh[N_NODES * 8];            // h @ W^T in fp16 (64 halves = 8 uint4/node)

// packed f32x2 helpers (Blackwell: only reachable via PTX)
#define PACK_F32X2(out, lo, hi) \
    asm("mov.b64 %0, {%1, %2};" : "=l"(out) : "f"(lo), "f"(hi))
#define UNPACK_F32X2(lo, hi, in) \
    asm("mov.b64 {%0, %1}, %2;" : "=f"(lo), "=f"(hi) : "l"(in))
#define FMA_F32X2(d, a, b, c) \
    asm("fma.rn.f32x2 %0, %1, %2, %3;" : "=l"(d) : "l"(a), "l"(b), "l"(c))

// ---------------------------------------------------------------------------
// Side stream + events + symbol address, created once at load time.
// ---------------------------------------------------------------------------
static cudaStream_t g_s2 = nullptr;
static cudaEvent_t  g_evFork = nullptr, g_evJoin = nullptr;
static void*        g_countPtr = nullptr;
namespace {
struct StreamInit {
    StreamInit() {
        if (cudaStreamCreateWithFlags(&g_s2, cudaStreamNonBlocking) != cudaSuccess)
            g_s2 = nullptr;
        if (cudaEventCreateWithFlags(&g_evFork, cudaEventDisableTiming) != cudaSuccess)
            g_evFork = nullptr;
        if (cudaEventCreateWithFlags(&g_evJoin, cudaEventDisableTiming) != cudaSuccess)
            g_evJoin = nullptr;
        if (cudaGetSymbolAddress(&g_countPtr, g_count) != cudaSuccess)
            g_countPtr = nullptr;
    }
} s_streamInit;
}

// ---------------------------------------------------------------------------
// K1 (fallback only): zero the degree histogram
// ---------------------------------------------------------------------------
__global__ void zero_count_kernel() {
    unsigned i = blockIdx.x * blockDim.x + threadIdx.x;
    if (i < N_NODES / 4) {
        reinterpret_cast<int4*>(g_count)[i] = make_int4(0, 0, 0, 0);
    }
}

// ---------------------------------------------------------------------------
// K2: direct bucket fill.  8 edges per thread (2 x int4 each of src/dst)
// -> ATOMG MLP 8.
// ---------------------------------------------------------------------------
__global__ __launch_bounds__(256)
void fill_kernel(const int4* __restrict__ src4, const int4* __restrict__ dst4) {
    unsigned q = (blockIdx.x * blockDim.x + threadIdx.x) * 2u;  // int4 pair idx
    if (q >= N_EDGES / 4) return;

    int4 sA = __ldg(&src4[q + 0]);
    int4 dA = __ldg(&dst4[q + 0]);
    int4 sB = __ldg(&src4[q + 1]);
    int4 dB = __ldg(&dst4[q + 1]);

    int pA0 = atomicAdd(&g_count[dA.x], 1);
    int pA1 = atomicAdd(&g_count[dA.y], 1);
    int pA2 = atomicAdd(&g_count[dA.z], 1);
    int pA3 = atomicAdd(&g_count[dA.w], 1);
    int pB0 = atomicAdd(&g_count[dB.x], 1);
    int pB1 = atomicAdd(&g_count[dB.y], 1);
    int pB2 = atomicAdd(&g_count[dB.z], 1);
    int pB3 = atomicAdd(&g_count[dB.w], 1);

    if (pA0 < CAP) g_bucket[dA.x * CAP + pA0] = sA.x;
    if (pA1 < CAP) g_bucket[dA.y * CAP + pA1] = sA.y;
    if (pA2 < CAP) g_bucket[dA.z * CAP + pA2] = sA.z;
    if (pA3 < CAP) g_bucket[dA.w * CAP + pA3] = sA.w;
    if (pB0 < CAP) g_bucket[dB.x * CAP + pB0] = sB.x;
    if (pB1 < CAP) g_bucket[dB.y * CAP + pB1] = sB.y;
    if (pB2 < CAP) g_bucket[dB.z * CAP + pB2] = sB.z;
    if (pB3 < CAP) g_bucket[dB.w * CAP + pB3] = sB.w;
}

// ---------------------------------------------------------------------------
// K3: hw = h @ W^T, fp16 output.  Register-tiled: block = 128 nodes x 64
// outs, thread = 4 nodes x 8 outs (16 f32x2 accumulators).  A transposed
// into smem [k][node], W transposed into smem [k][o].  Per k-step per
// thread: 3 x LDS.128 + 16 FFMA2.  LDS traffic ~21x lower than the old
// one-node-per-thread version (which was smem-crossbar-bound at ~43us).
// ---------------------------------------------------------------------------
__global__ __launch_bounds__(256)
void gemm_kernel(const float4* __restrict__ h4, const float* __restrict__ W) {
    __shared__ float As[FEATS][GBN];    // 32 KB  As[k][node]
    __shared__ float Ws[FEATS][FEATS];  // 16 KB  Ws[k][o] = W[o][k]

    const int tid = threadIdx.x;
    const unsigned base = blockIdx.x * GBN;

    // W transpose load
    for (int i = tid; i < FEATS * FEATS; i += 256) {
        Ws[i & 63][i >> 6] = W[i];
    }
    // A transpose load: i = k4*GBN + node (consecutive threads -> consecutive
    // nodes, conflict-free smem stores)
    for (int i = tid; i < 16 * GBN; i += 256) {
        int k4 = i >> 7;
        int node = i & (GBN - 1);
        unsigned gn = base + node;
        if (gn >= N_NODES) gn = N_NODES - 1;   // clamp (dup load, store guarded)
        float4 v = __ldg(&h4[gn * 16u + k4]);
        As[k4 * 4 + 0][node] = v.x;
        As[k4 * 4 + 1][node] = v.y;
        As[k4 * 4 + 2][node] = v.z;
        As[k4 * 4 + 3][node] = v.w;
    }
    __syncthreads();

    const int ng = tid >> 3;    // 0..31 -> nodes ng*4 .. ng*4+3
    const int og = tid & 7;     // 0..7  -> outs  og*8 .. og*8+7

    unsigned long long acc2[4][4];
    #pragma unroll
    for (int n = 0; n < 4; n++)
        #pragma unroll
        for (int j = 0; j < 4; j++)
            PACK_F32X2(acc2[n][j], 0.f, 0.f);

    #pragma unroll 4
    for (int k = 0; k < FEATS; k++) {
        float4 a = *reinterpret_cast<const float4*>(&As[k][ng * 4]);
        // W pairs load directly as packed 64-bit lanes
        ulonglong2 wA = *reinterpret_cast<const ulonglong2*>(&Ws[k][og * 8]);
        ulonglong2 wB = *reinterpret_cast<const ulonglong2*>(&Ws[k][og * 8 + 4]);
        float an[4] = {a.x, a.y, a.z, a.w};
        #pragma unroll
        for (int n = 0; n < 4; n++) {
            unsigned long long a2;
            PACK_F32X2(a2, an[n], an[n]);
            FMA_F32X2(acc2[n][0], a2, wA.x, acc2[n][0]);
            FMA_F32X2(acc2[n][1], a2, wA.y, acc2[n][1]);
            FMA_F32X2(acc2[n][2], a2, wB.x, acc2[n][2]);
            FMA_F32X2(acc2[n][3], a2, wB.y, acc2[n][3]);
        }
    }

    // epilogue: fp16 pack, one uint4 per node (outs og*8..og*8+7)
    #pragma unroll
    for (int n = 0; n < 4; n++) {
        unsigned gn = base + (unsigned)(ng * 4 + n);
        if (gn >= N_NODES) continue;
        uint4 pk;
        unsigned* pw = reinterpret_cast<unsigned*>(&pk);
        #pragma unroll
        for (int j = 0; j < 4; j++) {
            float lo, hi;
            UNPACK_F32X2(lo, hi, acc2[n][j]);
            __half2 hh = __floats2half2_rn(lo, hi);
            pw[j] = *reinterpret_cast<unsigned*>(&hh);
        }
        g_hwh[gn * 8u + og] = pk;
    }
}

// ---------------------------------------------------------------------------
// K4: gather-reduce over fp16 hw rows + bias + relu.
// 8 lanes per node; lane owns one uint4 (8 halves).  Indices loaded as int4
// (contiguous bucket rows); unroll x8 -> data-load MLP 8.  Pairwise HADD2
// then fp32 accumulate.
// ---------------------------------------------------------------------------
__global__ __launch_bounds__(256)
void gather_kernel(const float4* __restrict__ b4, float4* __restrict__ out4) {
    unsigned t = blockIdx.x * blockDim.x + threadIdx.x;   // < N*8 = 800k
    unsigned node = t >> 3;
    unsigned lane = t & 7;
    if (node >= N_NODES) return;

    int deg = __ldg(&g_count[node]);
    if (deg > CAP) deg = CAP;
    const int* row = g_bucket + node * CAP;

    float2 acc[4];
    #pragma unroll
    for (int j = 0; j < 4; j++) acc[j] = make_float2(0.f, 0.f);

    int i = 0;
    for (; i + 8 <= deg; i += 8) {
        int4 ia = __ldg(reinterpret_cast<const int4*>(row + i));
        int4 ib = __ldg(reinterpret_cast<const int4*>(row + i + 4));
        uint4 v0 = __ldg(&g_hwh[(unsigned)ia.x * 8u + lane]);
        uint4 v1 = __ldg(&g_hwh[(unsigned)ia.y * 8u + lane]);
        uint4 v2 = __ldg(&g_hwh[(unsigned)ia.z * 8u + lane]);
        uint4 v3 = __ldg(&g_hwh[(unsigned)ia.w * 8u + lane]);
        uint4 v4 = __ldg(&g_hwh[(unsigned)ib.x * 8u + lane]);
        uint4 v5 = __ldg(&g_hwh[(unsigned)ib.y * 8u + lane]);
        uint4 v6 = __ldg(&g_hwh[(unsigned)ib.z * 8u + lane]);
        uint4 v7 = __ldg(&g_hwh[(unsigned)ib.w * 8u + lane]);
        const __half2* p0 = reinterpret_cast<const __half2*>(&v0);
        const __half2* p1 = reinterpret_cast<const __half2*>(&v1);
        const __half2* p2 = reinterpret_cast<const __half2*>(&v2);
        const __half2* p3 = reinterpret_cast<const __half2*>(&v3);
        const __half2* p4 = reinterpret_cast<const __half2*>(&v4);
        const __half2* p5 = reinterpret_cast<const __half2*>(&v5);
        const __half2* p6 = reinterpret_cast<const __half2*>(&v6);
        const __half2* p7 = reinterpret_cast<const __half2*>(&v7);
        #pragma unroll
        for (int j = 0; j < 4; j++) {
            __half2 s01 = __hadd2(p0[j], p1[j]);   // depth-1 fp16 tree
            __half2 s23 = __hadd2(p2[j], p3[j]);
            __half2 s45 = __hadd2(p4[j], p5[j]);
            __half2 s67 = __hadd2(p6[j], p7[j]);
            float2 f01 = __half22float2(s01);
            float2 f23 = __half22float2(s23);
            float2 f45 = __half22float2(s45);
            float2 f67 = __half22float2(s67);
            acc[j].x += (f01.x + f23.x) + (f45.x + f67.x);
            acc[j].y += (f01.y + f23.y) + (f45.y + f67.y);
        }
    }
    for (; i + 4 <= deg; i += 4) {
        int4 ia = __ldg(reinterpret_cast<const int4*>(row + i));
        uint4 v0 = __ldg(&g_hwh[(unsigned)ia.x * 8u + lane]);
        uint4 v1 = __ldg(&g_hwh[(unsigned)ia.y * 8u + lane]);
        uint4 v2 = __ldg(&g_hwh[(unsigned)ia.z * 8u + lane]);
        uint4 v3 = __ldg(&g_hwh[(unsigned)ia.w * 8u + lane]);
        const __half2* p0 = reinterpret_cast<const __half2*>(&v0);
        const __half2* p1 = reinterpret_cast<const __half2*>(&v1);
        const __half2* p2 = reinterpret_cast<const __half2*>(&v2);
        const __half2* p3 = reinterpret_cast<const __half2*>(&v3);
        #pragma unroll
        for (int j = 0; j < 4; j++) {
            __half2 s01 = __hadd2(p0[j], p1[j]);
            __half2 s23 = __hadd2(p2[j], p3[j]);
            float2 f01 = __half22float2(s01);
            float2 f23 = __half22float2(s23);
            acc[j].x += f01.x + f23.x;
            acc[j].y += f01.y + f23.y;
        }
    }
    for (; i < deg; i++) {
        int s = __ldg(&row[i]);
        uint4 v = __ldg(&g_hwh[(unsigned)s * 8u + lane]);
        const __half2* p = reinterpret_cast<const __half2*>(&v);
        #pragma unroll
        for (int j = 0; j < 4; j++) {
            float2 f = __half22float2(p[j]);
            acc[j].x += f.x;
            acc[j].y += f.y;
        }
    }

    // bias + relu, write 8 floats = 2 float4
    float4 bia = __ldg(&b4[lane * 2 + 0]);
    float4 bib = __ldg(&b4[lane * 2 + 1]);
    float4 r0, r1;
    r0.x = fmaxf(acc[0].x + bia.x, 0.f);
    r0.y = fmaxf(acc[0].y + bia.y, 0.f);
    r0.z = fmaxf(acc[1].x + bia.z, 0.f);
    r0.w = fmaxf(acc[1].y + bia.w, 0.f);
    r1.x = fmaxf(acc[2].x + bib.x, 0.f);
    r1.y = fmaxf(acc[2].y + bib.y, 0.f);
    r1.z = fmaxf(acc[3].x + bib.z, 0.f);
    r1.w = fmaxf(acc[3].y + bib.w, 0.f);
    out4[node * 16u + lane * 2 + 0] = r0;
    out4[node * 16u + lane * 2 + 1] = r1;
}

// ---------------------------------------------------------------------------
// Launch:  stream0: memset(count) -> fill ---\
//          s2:      gemm (register-tiled) ----+--> gather(+bias+relu)
// ---------------------------------------------------------------------------
extern "C" void kernel_launch(void* const* d_in, const int* in_sizes, int n_in,
                              void* d_out, int out_size) {
    const float* h   = (const float*)d_in[0];
    const int*   src = (const int*)d_in[1];
    const int*   dst = (const int*)d_in[2];
    const float* W   = (const float*)d_in[3];
    const float* b   = (const float*)d_in[4];
    float4*      out = (float4*)d_out;

    (void)in_sizes; (void)n_in; (void)out_size;

    const bool fork = (g_s2 && g_evFork && g_evJoin);
    const unsigned fill_threads = N_EDGES / 8;            // 8 edges per thread
    const unsigned gemm_blocks = (N_NODES + GBN - 1) / GBN;

    if (fork) {
        cudaEventRecord(g_evFork, 0);
        cudaStreamWaitEvent(g_s2, g_evFork, 0);
        gemm_kernel<<<gemm_blocks, 256, 0, g_s2>>>((const float4*)h, W);
        cudaEventRecord(g_evJoin, g_s2);

        if (g_countPtr)
            cudaMemsetAsync(g_countPtr, 0, N_NODES * sizeof(int), 0);
        else
            zero_count_kernel<<<(N_NODES / 4 + 255) / 256, 256>>>();
        fill_kernel<<<(fill_threads + 255) / 256, 256>>>(
            (const int4*)src, (const int4*)dst);

        cudaStreamWaitEvent(0, g_evJoin, 0);
    } else {
        if (g_countPtr)
            cudaMemsetAsync(g_countPtr, 0, N_NODES * sizeof(int), 0);
        else
            zero_count_kernel<<<(N_NODES / 4 + 255) / 256, 256>>>();
        fill_kernel<<<(fill_threads + 255) / 256, 256>>>(
            (const int4*)src, (const int4*)dst);
        gemm_kernel<<<gemm_blocks, 256>>>((const float4*)h, W);
    }

    gather_kernel<<<(N_NODES * 8 + 255) / 256, 256>>>(
        (const float4*)b, out);
}

// round 11
// speedup vs baseline: 1.1701x; 1.1701x over previous
#include <cuda_runtime.h>
#include <cuda_fp16.h>
#include <cstdint>

#define N_NODES 100000
#define N_EDGES 1250000
#define FEATS   64
#define CAP     64            // bucket capacity per node (Poisson(12.5): P(>63) ~ 1e-30)
#define GBN     128           // gemm nodes per block

// ---------------------------------------------------------------------------
// Device-global scratch (no allocations allowed).
// ---------------------------------------------------------------------------
__device__ int   g_count[N_NODES];              // per-node in-degree
__device__ int   g_bucket[N_NODES * CAP];       // src ids, fixed stride
__device__ uint4 g_hwh[N_NODES * 8];            // h @ W^T in fp16 (64 halves = 8 uint4/node)

// packed f32x2 helpers (Blackwell: only reachable via PTX)
#define PACK_F32X2(out, lo, hi) \
    asm("mov.b64 %0, {%1, %2};" : "=l"(out) : "f"(lo), "f"(hi))
#define UNPACK_F32X2(lo, hi, in) \
    asm("mov.b64 {%0, %1}, %2;" : "=f"(lo), "=f"(hi) : "l"(in))
#define FMA_F32X2(d, a, b, c) \
    asm("fma.rn.f32x2 %0, %1, %2, %3;" : "=l"(d) : "l"(a), "l"(b), "l"(c))

// A-staging swizzle: 2-way max bank conflict on both store and compute-load.
__device__ __forceinline__ int swz(int node, int k4) {
    return node ^ (((node >> 4) & 7) << 2) ^ ((node >> 2) & 3)
                ^ (k4 & 3) ^ (((k4 >> 2) & 3) << 2);
}

// ---------------------------------------------------------------------------
// Side stream + events + symbol address, created once at load time.
// ---------------------------------------------------------------------------
static cudaStream_t g_s2 = nullptr;
static cudaEvent_t  g_evFork = nullptr, g_evJoin = nullptr;
static void*        g_countPtr = nullptr;
namespace {
struct StreamInit {
    StreamInit() {
        if (cudaStreamCreateWithFlags(&g_s2, cudaStreamNonBlocking) != cudaSuccess)
            g_s2 = nullptr;
        if (cudaEventCreateWithFlags(&g_evFork, cudaEventDisableTiming) != cudaSuccess)
            g_evFork = nullptr;
        if (cudaEventCreateWithFlags(&g_evJoin, cudaEventDisableTiming) != cudaSuccess)
            g_evJoin = nullptr;
        if (cudaGetSymbolAddress(&g_countPtr, g_count) != cudaSuccess)
            g_countPtr = nullptr;
    }
} s_streamInit;
}

// ---------------------------------------------------------------------------
// K1 (fallback only): zero the degree histogram
// ---------------------------------------------------------------------------
__global__ void zero_count_kernel() {
    unsigned i = blockIdx.x * blockDim.x + threadIdx.x;
    if (i < N_NODES / 4) {
        reinterpret_cast<int4*>(g_count)[i] = make_int4(0, 0, 0, 0);
    }
}

// ---------------------------------------------------------------------------
// K2: direct bucket fill.  8 edges per thread (2 x int4 each of src/dst)
// -> ATOMG MLP 8.
// ---------------------------------------------------------------------------
__global__ __launch_bounds__(256)
void fill_kernel(const int4* __restrict__ src4, const int4* __restrict__ dst4) {
    unsigned q = (blockIdx.x * blockDim.x + threadIdx.x) * 2u;  // int4 pair idx
    if (q >= N_EDGES / 4) return;

    int4 sA = __ldg(&src4[q + 0]);
    int4 dA = __ldg(&dst4[q + 0]);
    int4 sB = __ldg(&src4[q + 1]);
    int4 dB = __ldg(&dst4[q + 1]);

    int pA0 = atomicAdd(&g_count[dA.x], 1);
    int pA1 = atomicAdd(&g_count[dA.y], 1);
    int pA2 = atomicAdd(&g_count[dA.z], 1);
    int pA3 = atomicAdd(&g_count[dA.w], 1);
    int pB0 = atomicAdd(&g_count[dB.x], 1);
    int pB1 = atomicAdd(&g_count[dB.y], 1);
    int pB2 = atomicAdd(&g_count[dB.z], 1);
    int pB3 = atomicAdd(&g_count[dB.w], 1);

    if (pA0 < CAP) g_bucket[dA.x * CAP + pA0] = sA.x;
    if (pA1 < CAP) g_bucket[dA.y * CAP + pA1] = sA.y;
    if (pA2 < CAP) g_bucket[dA.z * CAP + pA2] = sA.z;
    if (pA3 < CAP) g_bucket[dA.w * CAP + pA3] = sA.w;
    if (pB0 < CAP) g_bucket[dB.x * CAP + pB0] = sB.x;
    if (pB1 < CAP) g_bucket[dB.y * CAP + pB1] = sB.y;
    if (pB2 < CAP) g_bucket[dB.z * CAP + pB2] = sB.z;
    if (pB3 < CAP) g_bucket[dB.w * CAP + pB3] = sB.w;
}

// ---------------------------------------------------------------------------
// K3: hw = h @ W^T, fp16 out.  Block = 128 nodes x 64 outs, 256 threads.
// Warp w owns out-group og=w (outs og*8..+7)  -> all W smem reads are
// warp-uniform broadcasts (conflict-free).  Lane owns 4 nodes (lane*4..+3).
// A staged in smem as [k4][node] float4 chunks with XOR swizzle (2-way max).
// Per k4 per thread: 4 A-LDS.128 + 8 broadcast W-LDS.128 -> 64 FFMA2.
// ---------------------------------------------------------------------------
__global__ __launch_bounds__(256)
void gemm_kernel(const float4* __restrict__ h4, const float* __restrict__ W) {
    __shared__ float4 As4[16][GBN];     // 32 KB, swizzled columns
    __shared__ float  Ws[FEATS][FEATS]; // 16 KB, Ws[k][o] = W[o][k]

    const int tid = threadIdx.x;
    const unsigned base = blockIdx.x * (unsigned)GBN;

    // Ws: o fast -> conflict-free smem stores (gmem reads strided but tiny)
    for (int i = tid; i < FEATS * FEATS; i += 256) {
        int o = i & 63, k = i >> 6;
        Ws[k][o] = __ldg(&W[o * 64 + k]);
    }
    // A: k4 fast -> fully coalesced gmem reads; swizzled smem stores
    for (int i = tid; i < 16 * GBN; i += 256) {
        int k4 = i & 15;
        int node = i >> 4;
        unsigned gn = base + (unsigned)node;
        if (gn >= N_NODES) gn = N_NODES - 1;   // clamp (dup load, store guarded later)
        float4 v = __ldg(&h4[gn * 16u + k4]);
        As4[k4][swz(node, k4)] = v;
    }
    __syncthreads();

    const int og = tid >> 5;     // warp id -> outs og*8..+7
    const int lane = tid & 31;   // nodes lane*4..+3

    unsigned long long acc[4][4];   // [node m][out-pair j]
    #pragma unroll
    for (int m = 0; m < 4; m++)
        #pragma unroll
        for (int j = 0; j < 4; j++)
            PACK_F32X2(acc[m][j], 0.f, 0.f);

    #pragma unroll 2
    for (int k4 = 0; k4 < 16; k4++) {
        float4 a[4];
        #pragma unroll
        for (int m = 0; m < 4; m++) {
            a[m] = As4[k4][swz(lane * 4 + m, k4)];
        }
        #pragma unroll
        for (int k = 0; k < 4; k++) {
            // warp-uniform broadcast loads; W pairs native as 64-bit lanes
            ulonglong2 wA = *reinterpret_cast<const ulonglong2*>(&Ws[k4 * 4 + k][og * 8]);
            ulonglong2 wB = *reinterpret_cast<const ulonglong2*>(&Ws[k4 * 4 + k][og * 8 + 4]);
            #pragma unroll
            for (int m = 0; m < 4; m++) {
                float ak = (k == 0) ? a[m].x : (k == 1) ? a[m].y
                         : (k == 2) ? a[m].z : a[m].w;
                unsigned long long a2;
                PACK_F32X2(a2, ak, ak);
                FMA_F32X2(acc[m][0], a2, wA.x, acc[m][0]);
                FMA_F32X2(acc[m][1], a2, wA.y, acc[m][1]);
                FMA_F32X2(acc[m][2], a2, wB.x, acc[m][2]);
                FMA_F32X2(acc[m][3], a2, wB.y, acc[m][3]);
            }
        }
    }

    // epilogue: fp16 pack, one uint4 per node (outs og*8..+7)
    #pragma unroll
    for (int m = 0; m < 4; m++) {
        unsigned gn = base + (unsigned)(lane * 4 + m);
        if (gn >= N_NODES) continue;
        uint4 pk;
        unsigned* pw = reinterpret_cast<unsigned*>(&pk);
        #pragma unroll
        for (int j = 0; j < 4; j++) {
            float lo, hi;
            UNPACK_F32X2(lo, hi, acc[m][j]);
            __half2 hh = __floats2half2_rn(lo, hi);
            pw[j] = *reinterpret_cast<unsigned*>(&hh);
        }
        g_hwh[gn * 8u + og] = pk;
    }
}

// ---------------------------------------------------------------------------
// K4: gather-reduce over fp16 hw rows + bias + relu.
// 8 lanes per node; lane owns one uint4 (8 halves).  Indices via int4;
// unroll x8 -> data-load MLP 8.  Pairwise HADD2 then fp32 accumulate.
// ---------------------------------------------------------------------------
__global__ __launch_bounds__(256)
void gather_kernel(const float4* __restrict__ b4, float4* __restrict__ out4) {
    unsigned t = blockIdx.x * blockDim.x + threadIdx.x;   // < N*8 = 800k
    unsigned node = t >> 3;
    unsigned lane = t & 7;
    if (node >= N_NODES) return;

    int deg = __ldg(&g_count[node]);
    if (deg > CAP) deg = CAP;
    const int* row = g_bucket + node * CAP;

    float2 acc[4];
    #pragma unroll
    for (int j = 0; j < 4; j++) acc[j] = make_float2(0.f, 0.f);

    int i = 0;
    for (; i + 8 <= deg; i += 8) {
        int4 ia = __ldg(reinterpret_cast<const int4*>(row + i));
        int4 ib = __ldg(reinterpret_cast<const int4*>(row + i + 4));
        uint4 v0 = __ldg(&g_hwh[(unsigned)ia.x * 8u + lane]);
        uint4 v1 = __ldg(&g_hwh[(unsigned)ia.y * 8u + lane]);
        uint4 v2 = __ldg(&g_hwh[(unsigned)ia.z * 8u + lane]);
        uint4 v3 = __ldg(&g_hwh[(unsigned)ia.w * 8u + lane]);
        uint4 v4 = __ldg(&g_hwh[(unsigned)ib.x * 8u + lane]);
        uint4 v5 = __ldg(&g_hwh[(unsigned)ib.y * 8u + lane]);
        uint4 v6 = __ldg(&g_hwh[(unsigned)ib.z * 8u + lane]);
        uint4 v7 = __ldg(&g_hwh[(unsigned)ib.w * 8u + lane]);
        const __half2* p0 = reinterpret_cast<const __half2*>(&v0);
        const __half2* p1 = reinterpret_cast<const __half2*>(&v1);
        const __half2* p2 = reinterpret_cast<const __half2*>(&v2);
        const __half2* p3 = reinterpret_cast<const __half2*>(&v3);
        const __half2* p4 = reinterpret_cast<const __half2*>(&v4);
        const __half2* p5 = reinterpret_cast<const __half2*>(&v5);
        const __half2* p6 = reinterpret_cast<const __half2*>(&v6);
        const __half2* p7 = reinterpret_cast<const __half2*>(&v7);
        #pragma unroll
        for (int j = 0; j < 4; j++) {
            __half2 s01 = __hadd2(p0[j], p1[j]);   // depth-1 fp16 tree
            __half2 s23 = __hadd2(p2[j], p3[j]);
            __half2 s45 = __hadd2(p4[j], p5[j]);
            __half2 s67 = __hadd2(p6[j], p7[j]);
            float2 f01 = __half22float2(s01);
            float2 f23 = __half22float2(s23);
            float2 f45 = __half22float2(s45);
            float2 f67 = __half22float2(s67);
            acc[j].x += (f01.x + f23.x) + (f45.x + f67.x);
            acc[j].y += (f01.y + f23.y) + (f45.y + f67.y);
        }
    }
    for (; i + 4 <= deg; i += 4) {
        int4 ia = __ldg(reinterpret_cast<const int4*>(row + i));
        uint4 v0 = __ldg(&g_hwh[(unsigned)ia.x * 8u + lane]);
        uint4 v1 = __ldg(&g_hwh[(unsigned)ia.y * 8u + lane]);
        uint4 v2 = __ldg(&g_hwh[(unsigned)ia.z * 8u + lane]);
        uint4 v3 = __ldg(&g_hwh[(unsigned)ia.w * 8u + lane]);
        const __half2* p0 = reinterpret_cast<const __half2*>(&v0);
        const __half2* p1 = reinterpret_cast<const __half2*>(&v1);
        const __half2* p2 = reinterpret_cast<const __half2*>(&v2);
        const __half2* p3 = reinterpret_cast<const __half2*>(&v3);
        #pragma unroll
        for (int j = 0; j < 4; j++) {
            __half2 s01 = __hadd2(p0[j], p1[j]);
            __half2 s23 = __hadd2(p2[j], p3[j]);
            float2 f01 = __half22float2(s01);
            float2 f23 = __half22float2(s23);
            acc[j].x += f01.x + f23.x;
            acc[j].y += f01.y + f23.y;
        }
    }
    for (; i < deg; i++) {
        int s = __ldg(&row[i]);
        uint4 v = __ldg(&g_hwh[(unsigned)s * 8u + lane]);
        const __half2* p = reinterpret_cast<const __half2*>(&v);
        #pragma unroll
        for (int j = 0; j < 4; j++) {
            float2 f = __half22float2(p[j]);
            acc[j].x += f.x;
            acc[j].y += f.y;
        }
    }

    float4 bia = __ldg(&b4[lane * 2 + 0]);
    float4 bib = __ldg(&b4[lane * 2 + 1]);
    float4 r0, r1;
    r0.x = fmaxf(acc[0].x + bia.x, 0.f);
    r0.y = fmaxf(acc[0].y + bia.y, 0.f);
    r0.z = fmaxf(acc[1].x + bia.z, 0.f);
    r0.w = fmaxf(acc[1].y + bia.w, 0.f);
    r1.x = fmaxf(acc[2].x + bib.x, 0.f);
    r1.y = fmaxf(acc[2].y + bib.y, 0.f);
    r1.z = fmaxf(acc[3].x + bib.z, 0.f);
    r1.w = fmaxf(acc[3].y + bib.w, 0.f);
    out4[node * 16u + lane * 2 + 0] = r0;
    out4[node * 16u + lane * 2 + 1] = r1;
}

// ---------------------------------------------------------------------------
// Launch:  stream0: memset(count) -> fill ---\
//          s2:      gemm (warp-uniform W) ----+--> gather(+bias+relu)
// ---------------------------------------------------------------------------
extern "C" void kernel_launch(void* const* d_in, const int* in_sizes, int n_in,
                              void* d_out, int out_size) {
    const float* h   = (const float*)d_in[0];
    const int*   src = (const int*)d_in[1];
    const int*   dst = (const int*)d_in[2];
    const float* W   = (const float*)d_in[3];
    const float* b   = (const float*)d_in[4];
    float4*      out = (float4*)d_out;

    (void)in_sizes; (void)n_in; (void)out_size;

    const bool fork = (g_s2 && g_evFork && g_evJoin);
    const unsigned fill_threads = N_EDGES / 8;            // 8 edges per thread
    const unsigned gemm_blocks = (N_NODES + GBN - 1) / GBN;

    if (fork) {
        cudaEventRecord(g_evFork, 0);
        cudaStreamWaitEvent(g_s2, g_evFork, 0);
        gemm_kernel<<<gemm_blocks, 256, 0, g_s2>>>((const float4*)h, W);
        cudaEventRecord(g_evJoin, g_s2);

        if (g_countPtr)
            cudaMemsetAsync(g_countPtr, 0, N_NODES * sizeof(int), 0);
        else
            zero_count_kernel<<<(N_NODES / 4 + 255) / 256, 256>>>();
        fill_kernel<<<(fill_threads + 255) / 256, 256>>>(
            (const int4*)src, (const int4*)dst);

        cudaStreamWaitEvent(0, g_evJoin, 0);
    } else {
        if (g_countPtr)
            cudaMemsetAsync(g_countPtr, 0, N_NODES * sizeof(int), 0);
        else
            zero_count_kernel<<<(N_NODES / 4 + 255) / 256, 256>>>();
        fill_kernel<<<(fill_threads + 255) / 256, 256>>>(
            (const int4*)src, (const int4*)dst);
        gemm_kernel<<<gemm_blocks, 256>>>((const float4*)h, W);
    }

    gather_kernel<<<(N_NODES * 8 + 255) / 256, 256>>>(
        (const float4*)b, out);
}